// round 1
// baseline (speedup 1.0000x reference)
#include <cuda_runtime.h>
#include <math.h>

#define VOCAB 30522
#define BB 2
#define SS 512
#define DD 768
#define JJ 12
#define KK 4
#define NT 1024          // B*S tokens
#define GDIM 9216        // J*D
#define FDIM 9984        // 13*D
#define NL 7
#define NLISTS (JJ*13)   // 156 (j, kb) block pairs

// ---- device scratch (no allocation allowed) ----
__device__ int   d_last[BB*VOCAB];          // last position per (batch, vocab id), -1 if absent
__device__ int   d_cnt[NLISTS];             // user count per (j, kb) list
__device__ int   d_users[NLISTS*NT];        // token ids per list
__device__ int   d_nzmask[NT];              // bitmask of nonzero fn blocks per token
__device__ float d_fn[(size_t)NT*JJ*DD];    // dense neighbor sums [t][j][d]
__device__ float d_g[(size_t)NT*GDIM];      // pre-sigmoid gate accumulator
__device__ float d_combined[(size_t)NT*2*DD]; // [mix ; seq]
__device__ float d_attnout[(size_t)NT*DD];

// ---------------------------------------------------------------- reset
__global__ void k_reset() {
    int i = blockIdx.x*blockDim.x + threadIdx.x;
    if (i < BB*VOCAB) d_last[i] = -1;
    if (i < NLISTS)   d_cnt[i]  = 0;
}

// ------------------------------------------------- dict build (last wins)
__global__ void k_scatter(const int* __restrict__ ids) {
    int i = blockIdx.x*blockDim.x + threadIdx.x;
    if (i < NT) {
        int b = i / SS, s = i % SS;
        atomicMax(&d_last[b*VOCAB + ids[i]], s);
    }
}

// ---------------------- gather neighbors, build nz masks + user lists
__global__ void k_fn(const float* __restrict__ seq, const int* __restrict__ nb) {
    int t = blockIdx.x;
    int b = t / SS;
    __shared__ int srcs[JJ*KK];
    int tid = threadIdx.x;
    if (tid < JJ*KK) {
        int id = nb[t*JJ*KK + tid];
        int src = -1;
        // batch b sees updates from batches <= b; latest batch wins
        for (int bb = b; bb >= 0; --bb) {
            int p = d_last[bb*VOCAB + id];
            if (p >= 0) { src = bb*SS + p; break; }
        }
        srcs[tid] = src;
    }
    __syncthreads();
    for (int j = 0; j < JJ; ++j) {
        int s0 = srcs[j*KK+0], s1 = srcs[j*KK+1], s2 = srcs[j*KK+2], s3 = srcs[j*KK+3];
        for (int d = tid; d < DD; d += blockDim.x) {
            float v = 0.f;
            if (s0 >= 0) v += seq[(size_t)s0*DD + d];
            if (s1 >= 0) v += seq[(size_t)s1*DD + d];
            if (s2 >= 0) v += seq[(size_t)s2*DD + d];
            if (s3 >= 0) v += seq[(size_t)s3*DD + d];
            d_fn[((size_t)t*JJ + j)*DD + d] = v;
        }
    }
    if (tid == 0) {
        int mask = 0;
        for (int j = 0; j < JJ; ++j) {
            bool any = (srcs[j*4]>=0)||(srcs[j*4+1]>=0)||(srcs[j*4+2]>=0)||(srcs[j*4+3]>=0);
            if (any) mask |= 1 << j;
        }
        d_nzmask[t] = mask;
        for (int j = 0; j < JJ; ++j) if ((mask >> j) & 1) {
            int i0 = atomicAdd(&d_cnt[j*13], 1);            // kb = 0 (seq block)
            d_users[(j*13)*NT + i0] = t;
            for (int j2 = 0; j2 < JJ; ++j2) if ((mask >> j2) & 1) {
                int L  = j*13 + j2 + 1;                     // kb = j2+1 (fn block)
                int i1 = atomicAdd(&d_cnt[L], 1);
                d_users[L*NT + i1] = t;
            }
        }
    }
}

// ------------------------------------------------------- g := bias
__global__ void k_initg(const float* __restrict__ bmlp) {
    size_t i = (size_t)blockIdx.x*blockDim.x + threadIdx.x;
    if (i < (size_t)NT*GDIM) d_g[i] = bmlp[i % GDIM];
}

// ------------------ block-sparse GEMM: g += A_block @ W_block^T
// grid (156 lists, 6 gi-tiles of 128, 64 user-chunks of 16), 256 threads
__global__ void k_bsgemm(const float* __restrict__ seq, const float* __restrict__ Wm) {
    int L  = blockIdx.x;
    int jb = L / 13, kb = L % 13;
    int U  = d_cnt[L];
    int u0 = blockIdx.z * 16;
    if (u0 >= U) return;
    int gi0 = blockIdx.y * 128;

    __shared__ float As[16][384];
    __shared__ float Ws[16][128];
    __shared__ int   st[16];

    int tid = threadIdx.x;
    if (tid < 16) {
        int u = u0 + tid;
        st[tid] = (u < U) ? d_users[L*NT + u] : -1;
    }
    __syncthreads();

    int ub = (tid >> 5) * 2;       // 2 users per thread
    int gv = (tid & 31) * 4;       // 4 outputs per thread
    float acc[2][4] = {};
    int colbase = kb * DD;         // kb=0 -> seq cols, kb>=1 -> fn block kb-1
    int wgi = tid & 127;
    int wfh = (tid >> 7) * 8;
    long wrowbase = (long)(jb*DD + gi0 + wgi) * FDIM + colbase + wfh;

    for (int half = 0; half < 2; ++half) {
        #pragma unroll
        for (int it = 0; it < 6; ++it) {           // 1536 float4 over 256 threads
            int idx = tid + it*256;
            int r = idx / 96, c4 = idx % 96;
            int tt = st[r];
            float4 v = make_float4(0.f, 0.f, 0.f, 0.f);
            if (tt >= 0) {
                const float* src = (kb == 0) ? (seq + (size_t)tt*DD)
                                             : (d_fn + ((size_t)tt*JJ + (kb-1))*DD);
                v = *(const float4*)(src + half*384 + c4*4);
            }
            *(float4*)&As[r][c4*4] = v;
        }
        __syncthreads();
        for (int fs = 0; fs < 384; fs += 16) {
            float4 w0 = *(const float4*)(Wm + wrowbase + half*384 + fs);
            float4 w1 = *(const float4*)(Wm + wrowbase + half*384 + fs + 4);
            Ws[wfh+0][wgi]=w0.x; Ws[wfh+1][wgi]=w0.y; Ws[wfh+2][wgi]=w0.z; Ws[wfh+3][wgi]=w0.w;
            Ws[wfh+4][wgi]=w1.x; Ws[wfh+5][wgi]=w1.y; Ws[wfh+6][wgi]=w1.z; Ws[wfh+7][wgi]=w1.w;
            __syncthreads();
            #pragma unroll
            for (int f = 0; f < 16; ++f) {
                float a0 = As[ub][fs+f];
                float a1 = As[ub+1][fs+f];
                float4 w = *(const float4*)&Ws[f][gv];
                acc[0][0] += a0*w.x; acc[0][1] += a0*w.y; acc[0][2] += a0*w.z; acc[0][3] += a0*w.w;
                acc[1][0] += a1*w.x; acc[1][1] += a1*w.y; acc[1][2] += a1*w.z; acc[1][3] += a1*w.w;
            }
            __syncthreads();
        }
    }
    #pragma unroll
    for (int r = 0; r < 2; ++r) {
        int tt = st[ub + r];
        if (tt >= 0) {
            float* gout = d_g + (size_t)tt*GDIM + jb*DD + gi0 + gv;
            atomicAdd(gout+0, acc[r][0]);
            atomicAdd(gout+1, acc[r][1]);
            atomicAdd(gout+2, acc[r][2]);
            atomicAdd(gout+3, acc[r][3]);
        }
    }
}

// ------- gating + Luong attention + softmax + combined = [mix ; seq]
__global__ void k_epilogue(const float* __restrict__ seq) {
    int t = blockIdx.x;
    __shared__ float sc[JJ][DD];
    __shared__ float ssc[JJ];
    int tid = threadIdx.x;
    if (tid < JJ) ssc[tid] = 0.f;
    __syncthreads();
    int mask = d_nzmask[t];
    for (int j = 0; j < JJ; ++j) if ((mask >> j) & 1) {
        float p = 0.f;
        for (int d = tid; d < DD; d += blockDim.x) {
            float gg = d_g[(size_t)t*GDIM + j*DD + d];
            float cv = d_fn[((size_t)t*JJ + j)*DD + d] / (1.f + __expf(-gg));
            sc[j][d] = cv;
            p += seq[(size_t)t*DD + d] * cv;
        }
        for (int off = 16; off; off >>= 1) p += __shfl_down_sync(0xffffffffu, p, off);
        if ((tid & 31) == 0) atomicAdd(&ssc[j], p);
    }
    __syncthreads();
    float m = -3.4e38f;
    for (int j = 0; j < JJ; ++j) m = fmaxf(m, ssc[j]);   // absent blocks score exactly 0
    float den = 0.f;
    for (int j = 0; j < JJ; ++j) den += __expf(ssc[j] - m);
    for (int d = tid; d < DD; d += blockDim.x) {
        float mix = 0.f;
        for (int j = 0; j < JJ; ++j) if ((mask >> j) & 1)
            mix += __expf(ssc[j] - m) * sc[j][d];
        mix /= den;
        d_combined[(size_t)t*1536 + d]      = mix;
        d_combined[(size_t)t*1536 + DD + d] = seq[(size_t)t*DD + d];
    }
}

// ---------------- attn_out = tanh(combined @ W_attn^T + b_attn)
// grid (64 row-chunks of 16, 6 gi-tiles of 128), 256 threads
__global__ void k_attn(const float* __restrict__ Wa, const float* __restrict__ ba) {
    int row0 = blockIdx.x * 16;
    int gi0  = blockIdx.y * 128;
    __shared__ float As[16][384];
    __shared__ float Ws[16][128];
    int tid = threadIdx.x;
    int ub = (tid >> 5) * 2, gv = (tid & 31) * 4;
    int wgi = tid & 127, wfh = (tid >> 7) * 8;
    long wrowbase = (long)(gi0 + wgi) * 1536 + wfh;
    float acc[2][4] = {};
    for (int ch = 0; ch < 4; ++ch) {
        #pragma unroll
        for (int it = 0; it < 6; ++it) {
            int idx = tid + it*256;
            int r = idx / 96, c4 = idx % 96;
            *(float4*)&As[r][c4*4] =
                *(const float4*)(d_combined + (size_t)(row0 + r)*1536 + ch*384 + c4*4);
        }
        __syncthreads();
        for (int fs = 0; fs < 384; fs += 16) {
            float4 w0 = *(const float4*)(Wa + wrowbase + ch*384 + fs);
            float4 w1 = *(const float4*)(Wa + wrowbase + ch*384 + fs + 4);
            Ws[wfh+0][wgi]=w0.x; Ws[wfh+1][wgi]=w0.y; Ws[wfh+2][wgi]=w0.z; Ws[wfh+3][wgi]=w0.w;
            Ws[wfh+4][wgi]=w1.x; Ws[wfh+5][wgi]=w1.y; Ws[wfh+6][wgi]=w1.z; Ws[wfh+7][wgi]=w1.w;
            __syncthreads();
            #pragma unroll
            for (int f = 0; f < 16; ++f) {
                float a0 = As[ub][fs+f];
                float a1 = As[ub+1][fs+f];
                float4 w = *(const float4*)&Ws[f][gv];
                acc[0][0] += a0*w.x; acc[0][1] += a0*w.y; acc[0][2] += a0*w.z; acc[0][3] += a0*w.w;
                acc[1][0] += a1*w.x; acc[1][1] += a1*w.y; acc[1][2] += a1*w.z; acc[1][3] += a1*w.w;
            }
            __syncthreads();
        }
    }
    #pragma unroll
    for (int r = 0; r < 2; ++r)
        #pragma unroll
        for (int c = 0; c < 4; ++c)
            d_attnout[(size_t)(row0 + ub + r)*DD + gi0 + gv + c] =
                tanhf(acc[r][c] + ba[gi0 + gv + c]);
}

// ---------------- logits = [seq ; attn_out] @ W_cls^T + b_cls
__global__ void k_logits(const float* __restrict__ seq, const float* __restrict__ Wc,
                         const float* __restrict__ bc, float* __restrict__ out) {
    int t = blockIdx.x;
    int w = threadIdx.x >> 5, lane = threadIdx.x & 31;
    float p = 0.f;
    for (int f = lane; f < 1536; f += 32) {
        float v = (f < DD) ? seq[(size_t)t*DD + f] : d_attnout[(size_t)t*DD + (f - DD)];
        p += v * Wc[w*1536 + f];
    }
    for (int off = 16; off; off >>= 1) p += __shfl_down_sync(0xffffffffu, p, off);
    if (lane == 0) out[t*NL + w] = p + bc[w];
}

extern "C" void kernel_launch(void* const* d_in, const int* in_sizes, int n_in,
                              void* d_out, int out_size) {
    const float* seq = (const float*)d_in[0];
    const int*   ids = (const int*)d_in[1];
    const int*   nb  = (const int*)d_in[2];
    const float* Wm  = (const float*)d_in[3];
    const float* bm  = (const float*)d_in[4];
    const float* Wa  = (const float*)d_in[5];
    const float* ba  = (const float*)d_in[6];
    const float* Wc  = (const float*)d_in[7];
    const float* bc  = (const float*)d_in[8];
    float* out = (float*)d_out;

    k_reset  <<<(BB*VOCAB + 255)/256, 256>>>();
    k_scatter<<<(NT + 255)/256, 256>>>(ids);
    k_fn     <<<NT, 256>>>(seq, nb);
    k_initg  <<<((size_t)NT*GDIM + 255)/256, 256>>>(bm);
    k_bsgemm <<<dim3(NLISTS, 6, 64), 256>>>(seq, Wm);
    k_epilogue<<<NT, 256>>>(seq);
    k_attn   <<<dim3(64, 6), 256>>>(Wa, ba);
    k_logits <<<NT, 224>>>(seq, Wc, bc, out);
}

// round 3
// speedup vs baseline: 1.1269x; 1.1269x over previous
#include <cuda_runtime.h>
#include <math.h>

#define VOCAB 30522
#define BB 2
#define SS 512
#define DD 768
#define JJ 12
#define KK 4
#define NT 1024          // B*S tokens
#define GDIM 9216        // J*D
#define FDIM 9984        // 13*D
#define NL 7
#define NLISTS (JJ*13)   // 156 (j, kb) block pairs

// ---- device scratch (no allocation allowed) ----
__device__ int   d_last[BB*VOCAB];
__device__ int   d_cnt[NLISTS];
__device__ int   d_users[NLISTS*NT];
__device__ int   d_nzmask[NT];
__device__ float d_fn[(size_t)NT*JJ*DD];
__device__ float d_g[(size_t)NT*GDIM];
__device__ float d_combined[(size_t)NT*2*DD];
__device__ float d_attnout[(size_t)NT*DD];

// ---------------------------------------------------------------- reset
__global__ void k_reset() {
    int i = blockIdx.x*blockDim.x + threadIdx.x;
    if (i < BB*VOCAB) d_last[i] = -1;
    if (i < NLISTS)   d_cnt[i]  = 0;
}

// ------------------------------------------------- dict build (last wins)
__global__ void k_scatter(const int* __restrict__ ids) {
    int i = blockIdx.x*blockDim.x + threadIdx.x;
    if (i < NT) {
        int b = i / SS, s = i % SS;
        atomicMax(&d_last[b*VOCAB + ids[i]], s);
    }
}

// ---------------------- gather neighbors, build nz masks + user lists
__global__ void k_fn(const float* __restrict__ seq, const int* __restrict__ nb) {
    int t = blockIdx.x;
    int b = t / SS;
    __shared__ int srcs[JJ*KK];
    int tid = threadIdx.x;
    if (tid < JJ*KK) {
        int id = nb[t*JJ*KK + tid];
        int src = -1;
        for (int bb = b; bb >= 0; --bb) {
            int p = d_last[bb*VOCAB + id];
            if (p >= 0) { src = bb*SS + p; break; }
        }
        srcs[tid] = src;
    }
    __syncthreads();
    for (int j = 0; j < JJ; ++j) {
        int s0 = srcs[j*KK+0], s1 = srcs[j*KK+1], s2 = srcs[j*KK+2], s3 = srcs[j*KK+3];
        if ((s0|s1|s2|s3) < 0 && s0<0 && s1<0 && s2<0 && s3<0) continue;  // zero block: skip write
        for (int d = tid; d < DD; d += blockDim.x) {
            float v = 0.f;
            if (s0 >= 0) v += seq[(size_t)s0*DD + d];
            if (s1 >= 0) v += seq[(size_t)s1*DD + d];
            if (s2 >= 0) v += seq[(size_t)s2*DD + d];
            if (s3 >= 0) v += seq[(size_t)s3*DD + d];
            d_fn[((size_t)t*JJ + j)*DD + d] = v;
        }
    }
    if (tid == 0) {
        int mask = 0;
        for (int j = 0; j < JJ; ++j) {
            bool any = (srcs[j*4]>=0)||(srcs[j*4+1]>=0)||(srcs[j*4+2]>=0)||(srcs[j*4+3]>=0);
            if (any) mask |= 1 << j;
        }
        d_nzmask[t] = mask;
        for (int j = 0; j < JJ; ++j) if ((mask >> j) & 1) {
            int i0 = atomicAdd(&d_cnt[j*13], 1);            // kb = 0 (seq block)
            d_users[(j*13)*NT + i0] = t;
            for (int j2 = 0; j2 < JJ; ++j2) if ((mask >> j2) & 1) {
                int L  = j*13 + j2 + 1;                     // kb = j2+1
                int i1 = atomicAdd(&d_cnt[L], 1);
                d_users[L*NT + i1] = t;
            }
        }
    }
}

// --------------------------- g := bias, only on present (t, jb) blocks
__global__ void k_initg(const float* __restrict__ bmlp) {
    int t = blockIdx.x;
    int mask = d_nzmask[t];
    int tid = threadIdx.x;
    for (int j = 0; j < JJ; ++j) if ((mask >> j) & 1)
        for (int d = tid; d < DD; d += blockDim.x)
            d_g[(size_t)t*GDIM + j*DD + d] = bmlp[j*DD + d];
}

// ------------------ block-sparse GEMM: g += A_block @ W_block^T
// grid (x=64 user-chunks of 16, y=6 gi-tiles of 128, z=156 lists), 256 threads.
// x-fastest launch order => consecutive CTAs share the W block (L2 reuse).
__global__ void k_bsgemm(const float* __restrict__ seq, const float* __restrict__ Wm) {
    int u0  = blockIdx.x * 16;
    int gi0 = blockIdx.y * 128;
    int L   = blockIdx.z;
    int U   = d_cnt[L];
    if (u0 >= U) return;
    int jb = L / 13, kb = L % 13;

    __shared__ __align__(16) float As[16][DD];   // 48 KB: full K for 16 users
    __shared__ __align__(16) float Ws[32][128];  // 16 KB: K-chunk of W
    __shared__ int st[16];

    int tid = threadIdx.x;
    if (tid < 16) {
        int u = u0 + tid;
        st[tid] = (u < U) ? d_users[L*NT + u] : -1;
    }
    __syncthreads();

    // A load: 16 threads per row, float4, 12 iters => 16 x 768
    {
        int r  = tid >> 4;
        int c0 = (tid & 15) * 4;
        int tt = st[r];
        const float* src = nullptr;
        if (tt >= 0) src = (kb == 0) ? (seq + (size_t)tt*DD)
                                     : (d_fn + ((size_t)tt*JJ + (kb-1))*DD);
        #pragma unroll
        for (int it = 0; it < 12; ++it) {
            int c = c0 + it*64;
            float4 v = src ? *(const float4*)(src + c) : make_float4(0.f,0.f,0.f,0.f);
            *(float4*)&As[r][c] = v;
        }
    }

    int ub = (tid >> 5) * 2;          // 2 users per thread (uniform per warp)
    int gv = (tid & 31) * 4;          // 4 outputs per thread
    int wgi = tid & 127;
    int wfh = (tid >> 7) * 16;        // 0 or 16: 16 K-cols per thread
    const float* wrow = Wm + (size_t)(jb*DD + gi0 + wgi) * FDIM + kb*DD;
    float acc[2][4] = {};

    for (int k0 = 0; k0 < DD; k0 += 32) {
        __syncthreads();              // also covers the initial A-load
        float4 w0 = *(const float4*)(wrow + k0 + wfh);
        float4 w1 = *(const float4*)(wrow + k0 + wfh + 4);
        float4 w2 = *(const float4*)(wrow + k0 + wfh + 8);
        float4 w3 = *(const float4*)(wrow + k0 + wfh + 12);
        Ws[wfh+ 0][wgi]=w0.x; Ws[wfh+ 1][wgi]=w0.y; Ws[wfh+ 2][wgi]=w0.z; Ws[wfh+ 3][wgi]=w0.w;
        Ws[wfh+ 4][wgi]=w1.x; Ws[wfh+ 5][wgi]=w1.y; Ws[wfh+ 6][wgi]=w1.z; Ws[wfh+ 7][wgi]=w1.w;
        Ws[wfh+ 8][wgi]=w2.x; Ws[wfh+ 9][wgi]=w2.y; Ws[wfh+10][wgi]=w2.z; Ws[wfh+11][wgi]=w2.w;
        Ws[wfh+12][wgi]=w3.x; Ws[wfh+13][wgi]=w3.y; Ws[wfh+14][wgi]=w3.z; Ws[wfh+15][wgi]=w3.w;
        __syncthreads();
        #pragma unroll
        for (int f = 0; f < 32; ++f) {
            float a0 = As[ub][k0+f];      // broadcast within warp
            float a1 = As[ub+1][k0+f];
            float4 w = *(const float4*)&Ws[f][gv];
            acc[0][0] += a0*w.x; acc[0][1] += a0*w.y; acc[0][2] += a0*w.z; acc[0][3] += a0*w.w;
            acc[1][0] += a1*w.x; acc[1][1] += a1*w.y; acc[1][2] += a1*w.z; acc[1][3] += a1*w.w;
        }
    }
    #pragma unroll
    for (int r = 0; r < 2; ++r) {
        int tt = st[ub + r];
        if (tt >= 0) {
            float* gout = d_g + (size_t)tt*GDIM + jb*DD + gi0 + gv;
            atomicAdd(gout+0, acc[r][0]);
            atomicAdd(gout+1, acc[r][1]);
            atomicAdd(gout+2, acc[r][2]);
            atomicAdd(gout+3, acc[r][3]);
        }
    }
}

// ------- gating + Luong attention + softmax + combined = [mix ; seq]
__global__ void k_epilogue(const float* __restrict__ seq) {
    int t = blockIdx.x;
    __shared__ float sc[JJ][DD];
    __shared__ float ssc[JJ];
    int tid = threadIdx.x;
    if (tid < JJ) ssc[tid] = 0.f;
    __syncthreads();
    int mask = d_nzmask[t];
    for (int j = 0; j < JJ; ++j) if ((mask >> j) & 1) {
        float p = 0.f;
        for (int d = tid; d < DD; d += blockDim.x) {
            float gg = d_g[(size_t)t*GDIM + j*DD + d];
            float cv = d_fn[((size_t)t*JJ + j)*DD + d] / (1.f + __expf(-gg));
            sc[j][d] = cv;
            p += seq[(size_t)t*DD + d] * cv;
        }
        for (int off = 16; off; off >>= 1) p += __shfl_down_sync(0xffffffffu, p, off);
        if ((tid & 31) == 0) atomicAdd(&ssc[j], p);
    }
    __syncthreads();
    float m = -3.4e38f;
    for (int j = 0; j < JJ; ++j) m = fmaxf(m, ssc[j]);
    float den = 0.f;
    for (int j = 0; j < JJ; ++j) den += __expf(ssc[j] - m);
    for (int d = tid; d < DD; d += blockDim.x) {
        float mix = 0.f;
        for (int j = 0; j < JJ; ++j) if ((mask >> j) & 1)
            mix += __expf(ssc[j] - m) * sc[j][d];
        mix /= den;
        d_combined[(size_t)t*1536 + d]      = mix;
        d_combined[(size_t)t*1536 + DD + d] = seq[(size_t)t*DD + d];
    }
}

// ---------------- attn_out = tanh(combined @ W_attn^T + b_attn)
// grid (x=64 row-chunks of 16, y=6 gi-tiles of 128), 256 threads
__global__ void k_attn(const float* __restrict__ Wa, const float* __restrict__ ba) {
    int row0 = blockIdx.x * 16;
    int gi0  = blockIdx.y * 128;
    __shared__ __align__(16) float As[16][DD];
    __shared__ __align__(16) float Ws[32][128];
    int tid = threadIdx.x;
    int ub = (tid >> 5) * 2, gv = (tid & 31) * 4;
    int wgi = tid & 127, wfh = (tid >> 7) * 16;
    float acc[2][4] = {};

    for (int half = 0; half < 2; ++half) {
        __syncthreads();   // protect As from previous half's readers
        {
            int r  = tid >> 4;
            int c0 = (tid & 15) * 4;
            const float* src = d_combined + (size_t)(row0 + r)*1536 + half*DD;
            #pragma unroll
            for (int it = 0; it < 12; ++it) {
                int c = c0 + it*64;
                *(float4*)&As[r][c] = *(const float4*)(src + c);
            }
        }
        const float* wrow = Wa + (size_t)(gi0 + wgi) * 1536 + half*DD;
        for (int k0 = 0; k0 < DD; k0 += 32) {
            __syncthreads();
            float4 w0 = *(const float4*)(wrow + k0 + wfh);
            float4 w1 = *(const float4*)(wrow + k0 + wfh + 4);
            float4 w2 = *(const float4*)(wrow + k0 + wfh + 8);
            float4 w3 = *(const float4*)(wrow + k0 + wfh + 12);
            Ws[wfh+ 0][wgi]=w0.x; Ws[wfh+ 1][wgi]=w0.y; Ws[wfh+ 2][wgi]=w0.z; Ws[wfh+ 3][wgi]=w0.w;
            Ws[wfh+ 4][wgi]=w1.x; Ws[wfh+ 5][wgi]=w1.y; Ws[wfh+ 6][wgi]=w1.z; Ws[wfh+ 7][wgi]=w1.w;
            Ws[wfh+ 8][wgi]=w2.x; Ws[wfh+ 9][wgi]=w2.y; Ws[wfh+10][wgi]=w2.z; Ws[wfh+11][wgi]=w2.w;
            Ws[wfh+12][wgi]=w3.x; Ws[wfh+13][wgi]=w3.y; Ws[wfh+14][wgi]=w3.z; Ws[wfh+15][wgi]=w3.w;
            __syncthreads();
            #pragma unroll
            for (int f = 0; f < 32; ++f) {
                float a0 = As[ub][k0+f];
                float a1 = As[ub+1][k0+f];
                float4 w = *(const float4*)&Ws[f][gv];
                acc[0][0] += a0*w.x; acc[0][1] += a0*w.y; acc[0][2] += a0*w.z; acc[0][3] += a0*w.w;
                acc[1][0] += a1*w.x; acc[1][1] += a1*w.y; acc[1][2] += a1*w.z; acc[1][3] += a1*w.w;
            }
        }
    }
    #pragma unroll
    for (int r = 0; r < 2; ++r)
        #pragma unroll
        for (int c = 0; c < 4; ++c)
            d_attnout[(size_t)(row0 + ub + r)*DD + gi0 + gv + c] =
                tanhf(acc[r][c] + ba[gi0 + gv + c]);
}

// ---------------- logits = [seq ; attn_out] @ W_cls^T + b_cls
__global__ void k_logits(const float* __restrict__ seq, const float* __restrict__ Wc,
                         const float* __restrict__ bc, float* __restrict__ out) {
    int t = blockIdx.x;
    int w = threadIdx.x >> 5, lane = threadIdx.x & 31;
    float p = 0.f;
    for (int f = lane; f < 1536; f += 32) {
        float v = (f < DD) ? seq[(size_t)t*DD + f] : d_attnout[(size_t)t*DD + (f - DD)];
        p += v * Wc[w*1536 + f];
    }
    for (int off = 16; off; off >>= 1) p += __shfl_down_sync(0xffffffffu, p, off);
    if (lane == 0) out[t*NL + w] = p + bc[w];
}

extern "C" void kernel_launch(void* const* d_in, const int* in_sizes, int n_in,
                              void* d_out, int out_size) {
    const float* seq = (const float*)d_in[0];
    const int*   ids = (const int*)d_in[1];
    const int*   nb  = (const int*)d_in[2];
    const float* Wm  = (const float*)d_in[3];
    const float* bm  = (const float*)d_in[4];
    const float* Wa  = (const float*)d_in[5];
    const float* ba  = (const float*)d_in[6];
    const float* Wc  = (const float*)d_in[7];
    const float* bc  = (const float*)d_in[8];
    float* out = (float*)d_out;

    k_reset   <<<(BB*VOCAB + 255)/256, 256>>>();
    k_scatter <<<(NT + 255)/256, 256>>>(ids);
    k_fn      <<<NT, 256>>>(seq, nb);
    k_initg   <<<NT, 256>>>(bm);
    k_bsgemm  <<<dim3(64, 6, NLISTS), 256>>>(seq, Wm);
    k_epilogue<<<NT, 256>>>(seq);
    k_attn    <<<dim3(64, 6), 256>>>(Wa, ba);
    k_logits  <<<NT, 224>>>(seq, Wc, bc, out);
}